// round 9
// baseline (speedup 1.0000x reference)
#include <cuda_runtime.h>
#include <math.h>

#define BATCH   64
#define MAXN    128
#define GH      64
#define GW      32
#define NPTS    2048        // GH*GW
#define NSPLIT  16
#define MAXCHUNK 8          // ceil(MAXN / NSPLIT)
#define NTHREADS 256
#define PPT     8           // NPTS / NTHREADS

// Partial accumulators: [BATCH][NSPLIT][NPTS] complex (float2) = 16 MB
__device__ float2 g_partial[BATCH * NSPLIT * NPTS];

// pos_w[k] = float32(0.1 * (10^(1/30))^k), computed in double like numpy
__device__ __forceinline__ float pos_w_val(int k) {
    return (float)(0.1 * pow(10.0, (double)k / 30.0));
}

__device__ __forceinline__ float frcp(float x) {
    float r; asm("rcp.approx.f32 %0, %1;" : "=f"(r) : "f"(x)); return r;
}

struct Tri { float xq, yq, xr, yr, xs, ys, area, scale2; };

__global__ __launch_bounds__(NTHREADS)
void pfc_accum_kernel(const float* __restrict__ tris,
                      const int* __restrict__ lengths) {
    __shared__ float sWx[GH];
    __shared__ float sWy[GW];
    __shared__ Tri   sTri[MAXCHUNK];
    // Packed tables (double buffered):
    //  A = (qcos, qsin, rcos, rsin)   B = (scos, ssin, qlin, rlin)
    __shared__ float4 sRowA[2][GH], sRowB[2][GH];
    __shared__ float4 sColA[2][GW], sColB[2][GW];

    const int tid = threadIdx.x;
    const int b   = blockIdx.x >> 4;        // / NSPLIT
    const int s   = blockIdx.x & (NSPLIT - 1);

    // Build frequency grid (once per block)
    if (tid < GH) {
        int h = tid;
        float v;
        if (h < 31)       v = -pos_w_val(30 - h);
        else if (h == 31) v = 0.0f;
        else if (h <= 62) v = pos_w_val(h - 32);
        else              v = 0.0f;           // padded row
        sWx[h] = v;
    } else if (tid < GH + GW) {
        int w = tid - GH;
        sWy[w] = (w == 0) ? 0.0f : pos_w_val(w - 1);
    }

    const float TWO_PI   = 6.28318530717958648f;
    const float FOUR_PI2 = 4.0f * 3.14159274101257324f * 3.14159274101257324f;

    const int len  = lengths[b];
    // interleaved assignment: this split owns triangles s, s+16, s+32, ...
    const int ntri = (len > s) ? ((len - 1 - s) / NSPLIT + 1) : 0;

    if (tid < MAXCHUNK && tid < ntri) {
        const int t = s + tid * NSPLIT;
        const float* p = tris + (size_t)(b * MAXN + t) * 6;
        Tri tr;
        tr.xq = p[0]; tr.yq = p[1];
        tr.xr = p[2]; tr.yr = p[3];
        tr.xs = p[4]; tr.ys = p[5];
        float det = tr.xq * (tr.yr - tr.ys) + tr.xr * (tr.ys - tr.yq)
                  + tr.xs * (tr.yq - tr.yr);
        tr.area   = fabsf(0.5f * det);
        tr.scale2 = 2.0f * tr.area / FOUR_PI2;
        sTri[tid] = tr;
    }
    __syncthreads();

    const int w     = tid & 31;
    const int hbase = (tid >> 5) * PPT;

    float accre[PPT], accim[PPT];
#pragma unroll
    for (int k = 0; k < PPT; k++) { accre[k] = 0.0f; accim[k] = 0.0f; }

    for (int j = 0; j < ntri; j++) {
        const Tri tr = sTri[j];   // broadcast
        const int buf = j & 1;

        // ---- build packed phasor tables (288 sincos, cooperative) ----
        if (tid < 192) {
            int h = tid & 63;
            int which = tid >> 6;               // 0:Q 1:R 2:S (row phasors)
            float wx = sWx[h];
            float arg, lin;
            if (which == 0)      { arg = wx * tr.xq; lin = wx * (tr.xr - tr.xq); }
            else if (which == 1) { arg = wx * tr.xr; lin = wx * (tr.xs - tr.xr); }
            else                 { arg = wx * tr.xs; lin = 0.0f; }
            float sn, cs;
            sincosf(-TWO_PI * arg, &sn, &cs);
            float* rowA = (float*)&sRowA[buf][h];
            float* rowB = (float*)&sRowB[buf][h];
            if (which == 0)      { rowA[0] = cs; rowA[1] = sn; rowB[2] = lin; }
            else if (which == 1) { rowA[2] = cs; rowA[3] = sn; rowB[3] = lin; }
            else                 { rowB[0] = cs; rowB[1] = sn; }
        } else {
            int ww = tid & 31;
            float wy = sWy[ww];
            float arg, lin;
            if (tid < 224) { arg = wy * tr.yq; lin = wy * (tr.yr - tr.yq); }
            else           { arg = wy * tr.yr; lin = wy * (tr.ys - tr.yr); }
            float sn, cs;
            sincosf(-TWO_PI * arg, &sn, &cs);
            float* colA = (float*)&sColA[buf][ww];
            float* colB = (float*)&sColB[buf][ww];
            if (tid < 224) { colA[0] = cs; colA[1] = sn; colB[2] = lin; }
            else           { colA[2] = cs; colA[3] = sn; colB[3] = lin; }
        }
        if (tid < 32) {                         // second job: colS
            float wy = sWy[tid];
            float sn, cs;
            sincosf(-TWO_PI * (wy * tr.ys), &sn, &cs);
            float* colB = (float*)&sColB[buf][tid];
            colB[0] = cs; colB[1] = sn;
        }
        __syncthreads();   // single barrier per triangle (double buffered)

        const float4 cA = sColA[buf][w];
        const float4 cB = sColB[buf][w];
        const float area   = tr.area;
        const float scale2 = tr.scale2;

#pragma unroll
        for (int k = 0; k < PPT; k++) {
            const int h = hbase + k;            // uniform across the warp
            const float4 rA = sRowA[buf][h];
            const float4 rB = sRowB[buf][h];

            const float U_ = rB.z + cB.z;       // wx*dxr + wy*dyr
            const float V_ = rB.w + cB.w;       // wx*dxs + wy*dys
            const float S  = U_ + V_;

            // vertex phasors: row x col unit-complex products
            const float eqR = rA.x * cA.x - rA.y * cA.y;
            const float eqI = rA.x * cA.y + rA.y * cA.x;
            const float erR = rA.z * cA.z - rA.w * cA.w;
            const float erI = rA.z * cA.w + rA.w * cA.z;
            const float esR = rB.x * cB.x - rB.y * cB.y;
            const float esI = rB.x * cB.y + rB.y * cB.x;

            if (U_ != 0.0f && V_ != 0.0f && S != 0.0f) {   // normal (hot)
                const float rU = frcp(U_);
                const float rV = frcp(V_);
                const float rS = frcp(S);
                const float t1  = scale2 * rU;
                const float t2  = scale2 * rV;
                const float cER =  t1 * rV;     //  scale2/(U*V)
                const float cEQ = -(t1 * rS);   // -scale2/(U*S)
                const float cES = -(t2 * rS);   // -scale2/(V*S)
                accre[k] += cES * esR + cER * erR + cEQ * eqR;
                accim[k] += cES * esI + cER * erI + cEQ * eqI;
            } else {                                       // rare specials
                const bool zero = (U_ == 0.0f) && (V_ == 0.0f);
                if (zero) {
                    accre[k] += area;
                } else if (S == 0.0f) {                    // diag
                    const float scale = -__fdividef(scale2, U_ * U_);
                    const float wim = TWO_PI * U_;
                    accre[k] += scale * (erR - eqR - wim * eqI);
                    accim[k] += scale * (erI - eqI + wim * eqR);
                } else if (U_ == 0.0f) {                   // u-mask
                    const float scale = -__fdividef(scale2, V_ * V_);
                    const float wim = TWO_PI * V_;
                    accre[k] += scale * (esR - eqR - wim * eqI);
                    accim[k] += scale * (esI - eqI + wim * eqR);
                } else {                                   // v-mask
                    const float scale = __fdividef(scale2, U_ * U_);
                    const float wim = TWO_PI * U_;
                    accre[k] += scale * (erR - wim * erI - eqR);
                    accim[k] += scale * (erI + wim * erR - eqI);
                }
            }
        }
        // next build writes the other buffer; the barrier at the top of
        // iteration j+1 orders build(j+2) after eval(j).
    }

#pragma unroll
    for (int k = 0; k < PPT; k++) {
        const int p = (hbase + k) * GW + w;
        g_partial[(b * NSPLIT + s) * NPTS + p] = make_float2(accre[k], accim[k]);
    }
}

__global__ __launch_bounds__(128)
void pfc_finalize_kernel(float* __restrict__ out) {
    const int idx = blockIdx.x * 128 + threadIdx.x;   // 0 .. BATCH*NPTS-1
    if (idx >= BATCH * NPTS) return;
    const int b = idx / NPTS;
    const int p = idx % NPTS;
    const int h = p >> 5;

    float re = 0.0f, im = 0.0f;
#pragma unroll
    for (int s = 0; s < NSPLIT; s++) {
        float2 v = g_partial[(b * NSPLIT + s) * NPTS + p];
        re += v.x; im += v.y;
    }

    float mag, phase;
    const float m2 = re * re + im * im;
    if (h == GH - 1 || m2 == 0.0f) {      // padded row, or zero total
        mag = 0.0f; phase = 0.0f;
    } else {
        mag   = log1pf(sqrtf(m2));
        phase = atan2f(im, re);
    }
    out[idx] = mag;                        // mag  block: [B,1,GH,GW]
    out[BATCH * NPTS + idx] = phase;       // phase block: [B,1,GH,GW]
}

extern "C" void kernel_launch(void* const* d_in, const int* in_sizes, int n_in,
                              void* d_out, int out_size) {
    const float* tris    = (const float*)d_in[0];   // [64,128,3,2] f32
    const int*   lengths = (const int*)d_in[1];     // [64] i32
    float* out = (float*)d_out;                     // 262144 f32: mag then phase

    pfc_accum_kernel<<<BATCH * NSPLIT, NTHREADS>>>(tris, lengths);
    pfc_finalize_kernel<<<(BATCH * NPTS + 127) / 128, 128>>>(out);
}

// round 11
// speedup vs baseline: 1.6122x; 1.6122x over previous
#include <cuda_runtime.h>
#include <math.h>

#define BATCH   64
#define MAXN    128
#define GH      64
#define GW      32
#define NPTS    2048        // GH*GW
#define NSPLIT  16
#define MAXCHUNK 8          // ceil(MAXN / NSPLIT)
#define NTHREADS 256
#define PPT     8           // NPTS / NTHREADS

typedef unsigned long long u64;

// Partial accumulators: [BATCH][NSPLIT][NPTS] complex (float2) = 16 MB
__device__ float2 g_partial[BATCH * NSPLIT * NPTS];
// Precomputed frequency grid (built once by init kernel, FP64 pow lives there)
__device__ float g_Wx[GH];
__device__ float g_Wy[GW];

// ---- packed f32x2 helpers ----
__device__ __forceinline__ u64 pk(float lo, float hi) {
    u64 r; asm("mov.b64 %0, {%1,%2};" : "=l"(r) : "f"(lo), "f"(hi)); return r;
}
__device__ __forceinline__ void upk(u64 v, float& lo, float& hi) {
    asm("mov.b64 {%0,%1}, %2;" : "=f"(lo), "=f"(hi) : "l"(v));
}
__device__ __forceinline__ u64 mul2(u64 a, u64 b) {
    u64 d; asm("mul.rn.f32x2 %0, %1, %2;" : "=l"(d) : "l"(a), "l"(b)); return d;
}
__device__ __forceinline__ u64 fma2(u64 a, u64 b, u64 c) {
    u64 d; asm("fma.rn.f32x2 %0, %1, %2, %3;" : "=l"(d) : "l"(a), "l"(b), "l"(c)); return d;
}
__device__ __forceinline__ u64 add2(u64 a, u64 b) {
    u64 d; asm("add.rn.f32x2 %0, %1, %2;" : "=l"(d) : "l"(a), "l"(b)); return d;
}

// pos_w[k] = float32(0.1 * (10^(1/30))^k), computed in double like numpy
__device__ __forceinline__ float pos_w_val(int k) {
    return (float)(0.1 * pow(10.0, (double)k / 30.0));
}

// One-time grid init: the ONLY place FP64 pow runs.
__global__ void pfc_init_grid_kernel() {
    const int tid = threadIdx.x;
    if (tid < GH) {
        int h = tid;
        float v;
        if (h < 31)       v = -pos_w_val(30 - h);
        else if (h == 31) v = 0.0f;
        else if (h <= 62) v = pos_w_val(h - 32);
        else              v = 0.0f;           // padded row
        g_Wx[h] = v;
    } else if (tid < GH + GW) {
        int w = tid - GH;
        g_Wy[w] = (w == 0) ? 0.0f : pos_w_val(w - 1);
    }
}

struct Tri { float xq, yq, xr, yr, xs, ys, area, scale2; };

__global__ __launch_bounds__(NTHREADS)
void pfc_accum_kernel(const float* __restrict__ tris,
                      const int* __restrict__ lengths) {
    __shared__ float sWx[GH];
    __shared__ float sWy[GW];
    __shared__ Tri   sTri[MAXCHUNK];
    // Row tables (per h): (cos, sin, -sin, lin). Q.lin = wx*dxr, R.lin = wx*dxs.
    __shared__ float4 sRowQ[2][GH], sRowR[2][GH];
    __shared__ float2 sRowP[2][GH];
    __shared__ float4 sColQ[2][GW], sColR[2][GW];
    __shared__ float2 sColP[2][GW];

    const int tid = threadIdx.x;
    const int b   = blockIdx.x >> 4;        // / NSPLIT
    const int s   = blockIdx.x & (NSPLIT - 1);

    // Load precomputed frequency grid (no FP64 here)
    if (tid < GH)                sWx[tid] = g_Wx[tid];
    else if (tid < GH + GW)      sWy[tid - GH] = g_Wy[tid - GH];

    const float TWO_PI   = 6.28318530717958648f;
    const float FOUR_PI2 = 4.0f * 3.14159274101257324f * 3.14159274101257324f;

    const int len  = lengths[b];
    // interleaved assignment: this split owns triangles s, s+16, s+32, ...
    const int ntri = (len > s) ? ((len - 1 - s) / NSPLIT + 1) : 0;

    if (tid < MAXCHUNK && tid < ntri) {
        const int t = s + tid * NSPLIT;
        const float* p = tris + (size_t)(b * MAXN + t) * 6;
        Tri tr;
        tr.xq = p[0]; tr.yq = p[1];
        tr.xr = p[2]; tr.yr = p[3];
        tr.xs = p[4]; tr.ys = p[5];
        float det = tr.xq * (tr.yr - tr.ys) + tr.xr * (tr.ys - tr.yq)
                  + tr.xs * (tr.yq - tr.yr);
        tr.area   = fabsf(0.5f * det);
        tr.scale2 = 2.0f * tr.area / FOUR_PI2;
        sTri[tid] = tr;
    }
    __syncthreads();

    const int w     = tid & 31;
    const int hbase = (tid >> 5) * PPT;

    u64 acc[PPT];
#pragma unroll
    for (int k = 0; k < PPT; k++) acc[k] = 0ull;

    for (int j = 0; j < ntri; j++) {
        const Tri tr = sTri[j];   // broadcast
        const int buf = j & 1;

        // ---- build factored vertex-phasor tables (288 sincos, coop) ----
        if (tid < 192) {
            int h = tid & 63;
            int which = tid >> 6;               // 0:Q 1:R 2:P(=S row)
            float wx = sWx[h];
            float arg, lin;
            if (which == 0)      { arg = wx * tr.xq; lin = wx * (tr.xr - tr.xq); }
            else if (which == 1) { arg = wx * tr.xr; lin = wx * (tr.xs - tr.xr); }
            else                 { arg = wx * tr.xs; lin = 0.0f; }
            float sn, cs;
            sincosf(-TWO_PI * arg, &sn, &cs);
            if (which == 0)      sRowQ[buf][h] = make_float4(cs, sn, -sn, lin);
            else if (which == 1) sRowR[buf][h] = make_float4(cs, sn, -sn, lin);
            else                 sRowP[buf][h] = make_float2(cs, sn);
        } else {
            int ww = tid & 31;
            float wy = sWy[ww];
            float arg, lin;
            if (tid < 224) { arg = wy * tr.yq; lin = wy * (tr.yr - tr.yq); }
            else           { arg = wy * tr.yr; lin = wy * (tr.ys - tr.yr); }
            float sn, cs;
            sincosf(-TWO_PI * arg, &sn, &cs);
            if (tid < 224) sColQ[buf][ww] = make_float4(cs, sn, lin, 0.0f);
            else           sColR[buf][ww] = make_float4(cs, sn, lin, 0.0f);
        }
        if (tid < 32) {                         // second job: colS phasor
            float wy = sWy[tid];
            float sn, cs;
            sincosf(-TWO_PI * (wy * tr.ys), &sn, &cs);
            sColP[buf][tid] = make_float2(cs, sn);
        }
        __syncthreads();   // single barrier per triangle (double buffered)

        // ---- per-triangle column prep (done once, reused over 8 h's) ----
        const float4 cQ = sColQ[buf][w];
        const float4 cR = sColR[buf][w];
        const float2 cS = sColP[buf][w];
        const u64 cQcdN = pk(-cQ.x, -cQ.y);     // negated -> produces -Eq
        const u64 cQdcN = pk(-cQ.y, -cQ.x);
        const u64 cRcd  = pk( cR.x,  cR.y);     // positive -> Er
        const u64 cRdc  = pk( cR.y,  cR.x);
        const u64 cScdN = pk(-cS.x, -cS.y);     // negated -> -Es
        const u64 cSdcN = pk(-cS.y, -cS.x);
        const float cLinU = cQ.z;
        const float cLinV = cR.z;
        const float area   = tr.area;
        const float scale2 = tr.scale2;

#pragma unroll
        for (int k = 0; k < PPT; k++) {
            const int h = hbase + k;            // uniform across the warp
            const float4 rQ = sRowQ[buf][h];
            const float4 rR = sRowR[buf][h];
            const float2 rP = sRowP[buf][h];

            const float U_ = rQ.w + cLinU;
            const float V_ = rR.w + cLinV;
            const float S  = U_ + V_;

            // vertex phasors (row x col complex product), Q and S negated
            u64 EqN = mul2(pk(rQ.x, rQ.x), cQcdN);
            EqN     = fma2(pk(rQ.z, rQ.y), cQdcN, EqN);
            u64 Er  = mul2(pk(rR.x, rR.x), cRcd);
            Er      = fma2(pk(rR.z, rR.y), cRdc, Er);
            u64 EsN = mul2(pk(rP.x, rP.x), cScdN);
            EsN     = fma2(pk(-rP.y, rP.y), cSdcN, EsN);

            if (U_ != 0.0f && V_ != 0.0f && S != 0.0f) {          // normal
                // p2 = -U_*Es + S*Er - V_*Eq  =  U_*EsN + S*Er + V_*EqN
                u64 p2 = mul2(pk(U_, U_), EsN);
                p2 = fma2(pk(S, S), Er, p2);
                p2 = fma2(pk(V_, V_), EqN, p2);
                const float scale = __fdividef(scale2, U_ * V_ * S);
                acc[k] = fma2(pk(scale, scale), p2, acc[k]);
            } else {
                float eqr, eqi, esr, esi, erre, erim;
                upk(EqN, eqr, eqi); eqr = -eqr; eqi = -eqi;
                upk(EsN, esr, esi); esr = -esr; esi = -esi;
                upk(Er, erre, erim);
                if (U_ == 0.0f && V_ == 0.0f) {                   // zero
                    acc[k] = add2(acc[k], pk(area, 0.0f));
                } else if (S == 0.0f) {                           // diag
                    const float scale = -__fdividef(scale2, U_ * U_);
                    const float wim = TWO_PI * U_;
                    const float tre = erre - eqr - wim * eqi;
                    const float tim = erim - eqi + wim * eqr;
                    acc[k] = fma2(pk(scale, scale), pk(tre, tim), acc[k]);
                } else if (U_ == 0.0f) {                          // u-mask
                    const float scale = -__fdividef(scale2, V_ * V_);
                    const float wim = TWO_PI * V_;
                    const float tre = esr - eqr - wim * eqi;
                    const float tim = esi - eqi + wim * eqr;
                    acc[k] = fma2(pk(scale, scale), pk(tre, tim), acc[k]);
                } else {                                          // v-mask
                    const float scale = __fdividef(scale2, U_ * U_);
                    const float wim = TWO_PI * U_;
                    const float tre = erre - wim * erim - eqr;
                    const float tim = erim + wim * erre - eqi;
                    acc[k] = fma2(pk(scale, scale), pk(tre, tim), acc[k]);
                }
            }
        }
        // next build writes the other buffer; the barrier at the top of
        // iteration j+1 orders build(j+2) after eval(j).
    }

#pragma unroll
    for (int k = 0; k < PPT; k++) {
        const int p = (hbase + k) * GW + w;
        *reinterpret_cast<u64*>(&g_partial[(b * NSPLIT + s) * NPTS + p]) = acc[k];
    }
}

__global__ __launch_bounds__(128)
void pfc_finalize_kernel(float* __restrict__ out) {
    const int idx = blockIdx.x * 128 + threadIdx.x;   // 0 .. BATCH*NPTS-1
    if (idx >= BATCH * NPTS) return;
    const int b = idx / NPTS;
    const int p = idx % NPTS;
    const int h = p >> 5;

    float re = 0.0f, im = 0.0f;
#pragma unroll
    for (int s = 0; s < NSPLIT; s++) {
        float2 v = g_partial[(b * NSPLIT + s) * NPTS + p];
        re += v.x; im += v.y;
    }

    float mag, phase;
    const float m2 = re * re + im * im;
    if (h == GH - 1 || m2 == 0.0f) {      // padded row, or zero total
        mag = 0.0f; phase = 0.0f;
    } else {
        mag   = log1pf(sqrtf(m2));
        phase = atan2f(im, re);
    }
    out[idx] = mag;                        // mag  block: [B,1,GH,GW]
    out[BATCH * NPTS + idx] = phase;       // phase block: [B,1,GH,GW]
}

extern "C" void kernel_launch(void* const* d_in, const int* in_sizes, int n_in,
                              void* d_out, int out_size) {
    const float* tris    = (const float*)d_in[0];   // [64,128,3,2] f32
    const int*   lengths = (const int*)d_in[1];     // [64] i32
    float* out = (float*)d_out;                     // 262144 f32: mag then phase

    pfc_init_grid_kernel<<<1, GH + GW>>>();
    pfc_accum_kernel<<<BATCH * NSPLIT, NTHREADS>>>(tris, lengths);
    pfc_finalize_kernel<<<(BATCH * NPTS + 127) / 128, 128>>>(out);
}

// round 12
// speedup vs baseline: 1.7120x; 1.0619x over previous
#include <cuda_runtime.h>
#include <math.h>

#define BATCH   64
#define MAXN    128
#define GH      64
#define GW      32
#define NPTS    2048        // GH*GW
#define NSPLIT  16
#define MAXCHUNK 8          // ceil(MAXN / NSPLIT)
#define NTHREADS 256
#define PPT     8           // NPTS / NTHREADS

typedef unsigned long long u64;

// Partial accumulators: [BATCH][NSPLIT][NPTS] complex (float2) = 16 MB
__device__ float2 g_partial[BATCH * NSPLIT * NPTS];
// Precomputed frequency grid (built once by init kernel, FP64 pow lives there)
__device__ float g_Wx[GH];
__device__ float g_Wy[GW];

// ---- packed f32x2 helpers ----
__device__ __forceinline__ u64 pk(float lo, float hi) {
    u64 r; asm("mov.b64 %0, {%1,%2};" : "=l"(r) : "f"(lo), "f"(hi)); return r;
}
__device__ __forceinline__ void upk(u64 v, float& lo, float& hi) {
    asm("mov.b64 {%0,%1}, %2;" : "=f"(lo), "=f"(hi) : "l"(v));
}
__device__ __forceinline__ u64 mul2(u64 a, u64 b) {
    u64 d; asm("mul.rn.f32x2 %0, %1, %2;" : "=l"(d) : "l"(a), "l"(b)); return d;
}
__device__ __forceinline__ u64 fma2(u64 a, u64 b, u64 c) {
    u64 d; asm("fma.rn.f32x2 %0, %1, %2, %3;" : "=l"(d) : "l"(a), "l"(b), "l"(c)); return d;
}
__device__ __forceinline__ u64 add2(u64 a, u64 b) {
    u64 d; asm("add.rn.f32x2 %0, %1, %2;" : "=l"(d) : "l"(a), "l"(b)); return d;
}

// pos_w[k] = float32(0.1 * (10^(1/30))^k), computed in double like numpy
__device__ __forceinline__ float pos_w_val(int k) {
    return (float)(0.1 * pow(10.0, (double)k / 30.0));
}

// One-time grid init. One thread PER BLOCK so each FP64 pow chain runs on its
// own SM at pure latency (no DP-unit throughput serialization).
__global__ void pfc_init_grid_kernel() {
    const int i = blockIdx.x;
    if (i < GH) {
        int h = i;
        float v;
        if (h < 31)       v = -pos_w_val(30 - h);
        else if (h == 31) v = 0.0f;
        else if (h <= 62) v = pos_w_val(h - 32);
        else              v = 0.0f;           // padded row
        g_Wx[h] = v;
    } else {
        int w = i - GH;
        g_Wy[w] = (w == 0) ? 0.0f : pos_w_val(w - 1);
    }
}

struct Tri { float xq, yq, xr, yr, xs, ys, area, scale2; };

__global__ __launch_bounds__(NTHREADS)
void pfc_accum_kernel(const float* __restrict__ tris,
                      const int* __restrict__ lengths) {
    __shared__ float sWx[GH];
    __shared__ float sWy[GW];
    __shared__ Tri   sTri[MAXCHUNK];
    __shared__ float4 sRowQ[2][GH], sRowR[2][GH];
    __shared__ float2 sRowP[2][GH];
    __shared__ float4 sColQ[2][GW], sColR[2][GW];
    __shared__ float2 sColP[2][GW];

    const int tid = threadIdx.x;
    const int b   = blockIdx.x >> 4;        // / NSPLIT
    const int s   = blockIdx.x & (NSPLIT - 1);

    // Load precomputed frequency grid (no FP64 here)
    if (tid < GH)                sWx[tid] = g_Wx[tid];
    else if (tid < GH + GW)      sWy[tid - GH] = g_Wy[tid - GH];

    const float TWO_PI   = 6.28318530717958648f;
    const float FOUR_PI2 = 4.0f * 3.14159274101257324f * 3.14159274101257324f;

    const int len  = lengths[b];
    // interleaved assignment: this split owns triangles s, s+16, s+32, ...
    const int ntri = (len > s) ? ((len - 1 - s) / NSPLIT + 1) : 0;

    if (tid < MAXCHUNK && tid < ntri) {
        const int t = s + tid * NSPLIT;
        const float* p = tris + (size_t)(b * MAXN + t) * 6;
        Tri tr;
        tr.xq = p[0]; tr.yq = p[1];
        tr.xr = p[2]; tr.yr = p[3];
        tr.xs = p[4]; tr.ys = p[5];
        float det = tr.xq * (tr.yr - tr.ys) + tr.xr * (tr.ys - tr.yq)
                  + tr.xs * (tr.yq - tr.yr);
        tr.area   = fabsf(0.5f * det);
        tr.scale2 = 2.0f * tr.area / FOUR_PI2;
        sTri[tid] = tr;
    }
    __syncthreads();

    const int w     = tid & 31;
    const int hbase = (tid >> 5) * PPT;

    u64 acc[PPT];
#pragma unroll
    for (int k = 0; k < PPT; k++) acc[k] = 0ull;

    for (int j = 0; j < ntri; j++) {
        const Tri tr = sTri[j];   // broadcast
        const int buf = j & 1;

        // ---- build factored vertex-phasor tables (288 sincos, coop) ----
        if (tid < 192) {
            int h = tid & 63;
            int which = tid >> 6;               // 0:Q 1:R 2:P(=S row)
            float wx = sWx[h];
            float arg, lin;
            if (which == 0)      { arg = wx * tr.xq; lin = wx * (tr.xr - tr.xq); }
            else if (which == 1) { arg = wx * tr.xr; lin = wx * (tr.xs - tr.xr); }
            else                 { arg = wx * tr.xs; lin = 0.0f; }
            float sn, cs;
            sincosf(-TWO_PI * arg, &sn, &cs);
            if (which == 0)      sRowQ[buf][h] = make_float4(cs, sn, -sn, lin);
            else if (which == 1) sRowR[buf][h] = make_float4(cs, sn, -sn, lin);
            else                 sRowP[buf][h] = make_float2(cs, sn);
        } else {
            int ww = tid & 31;
            float wy = sWy[ww];
            float arg, lin;
            if (tid < 224) { arg = wy * tr.yq; lin = wy * (tr.yr - tr.yq); }
            else           { arg = wy * tr.yr; lin = wy * (tr.ys - tr.yr); }
            float sn, cs;
            sincosf(-TWO_PI * arg, &sn, &cs);
            if (tid < 224) sColQ[buf][ww] = make_float4(cs, sn, lin, 0.0f);
            else           sColR[buf][ww] = make_float4(cs, sn, lin, 0.0f);
        }
        if (tid < 32) {                         // second job: colS phasor
            float wy = sWy[tid];
            float sn, cs;
            sincosf(-TWO_PI * (wy * tr.ys), &sn, &cs);
            sColP[buf][tid] = make_float2(cs, sn);
        }
        __syncthreads();   // single barrier per triangle (double buffered)

        // ---- per-triangle column prep (done once, reused over 8 h's) ----
        const float4 cQ = sColQ[buf][w];
        const float4 cR = sColR[buf][w];
        const float2 cS = sColP[buf][w];
        const u64 cQcdN = pk(-cQ.x, -cQ.y);     // negated -> produces -Eq
        const u64 cQdcN = pk(-cQ.y, -cQ.x);
        const u64 cRcd  = pk( cR.x,  cR.y);     // positive -> Er
        const u64 cRdc  = pk( cR.y,  cR.x);
        const u64 cScdN = pk(-cS.x, -cS.y);     // negated -> -Es
        const u64 cSdcN = pk(-cS.y, -cS.x);
        const float cLinU = cQ.z;
        const float cLinV = cR.z;
        const float area   = tr.area;
        const float scale2 = tr.scale2;

#pragma unroll
        for (int k = 0; k < PPT; k++) {
            const int h = hbase + k;            // uniform across the warp
            const float4 rQ = sRowQ[buf][h];
            const float4 rR = sRowR[buf][h];
            const float2 rP = sRowP[buf][h];

            const float U_ = rQ.w + cLinU;
            const float V_ = rR.w + cLinV;
            const float S  = U_ + V_;

            // vertex phasors (row x col complex product), Q and S negated
            u64 EqN = mul2(pk(rQ.x, rQ.x), cQcdN);
            EqN     = fma2(pk(rQ.z, rQ.y), cQdcN, EqN);
            u64 Er  = mul2(pk(rR.x, rR.x), cRcd);
            Er      = fma2(pk(rR.z, rR.y), cRdc, Er);
            u64 EsN = mul2(pk(rP.x, rP.x), cScdN);
            EsN     = fma2(pk(-rP.y, rP.y), cSdcN, EsN);

            if (U_ != 0.0f && V_ != 0.0f && S != 0.0f) {          // normal
                // p2 = -U_*Es + S*Er - V_*Eq  =  U_*EsN + S*Er + V_*EqN
                u64 p2 = mul2(pk(U_, U_), EsN);
                p2 = fma2(pk(S, S), Er, p2);
                p2 = fma2(pk(V_, V_), EqN, p2);
                const float scale = __fdividef(scale2, U_ * V_ * S);
                acc[k] = fma2(pk(scale, scale), p2, acc[k]);
            } else {
                float eqr, eqi, esr, esi, erre, erim;
                upk(EqN, eqr, eqi); eqr = -eqr; eqi = -eqi;
                upk(EsN, esr, esi); esr = -esr; esi = -esi;
                upk(Er, erre, erim);
                if (U_ == 0.0f && V_ == 0.0f) {                   // zero
                    acc[k] = add2(acc[k], pk(area, 0.0f));
                } else if (S == 0.0f) {                           // diag
                    const float scale = -__fdividef(scale2, U_ * U_);
                    const float wim = TWO_PI * U_;
                    const float tre = erre - eqr - wim * eqi;
                    const float tim = erim - eqi + wim * eqr;
                    acc[k] = fma2(pk(scale, scale), pk(tre, tim), acc[k]);
                } else if (U_ == 0.0f) {                          // u-mask
                    const float scale = -__fdividef(scale2, V_ * V_);
                    const float wim = TWO_PI * V_;
                    const float tre = esr - eqr - wim * eqi;
                    const float tim = esi - eqi + wim * eqr;
                    acc[k] = fma2(pk(scale, scale), pk(tre, tim), acc[k]);
                } else {                                          // v-mask
                    const float scale = __fdividef(scale2, U_ * U_);
                    const float wim = TWO_PI * U_;
                    const float tre = erre - wim * erim - eqr;
                    const float tim = erim + wim * erre - eqi;
                    acc[k] = fma2(pk(scale, scale), pk(tre, tim), acc[k]);
                }
            }
        }
        // next build writes the other buffer; the barrier at the top of
        // iteration j+1 orders build(j+2) after eval(j).
    }

#pragma unroll
    for (int k = 0; k < PPT; k++) {
        const int p = (hbase + k) * GW + w;
        *reinterpret_cast<u64*>(&g_partial[(b * NSPLIT + s) * NPTS + p]) = acc[k];
    }
}

// Two threads per point: each sums 8 of the 16 stages, exchange via smem,
// then half-0 writes mag and half-1 writes phase.
__global__ __launch_bounds__(256)
void pfc_finalize_kernel(float* __restrict__ out) {
    __shared__ float2 sPart[256];
    const int tid  = threadIdx.x;
    const int lp   = tid & 127;               // local point
    const int half = tid >> 7;                // 0: stages 0-7, 1: stages 8-15
    const int idx  = blockIdx.x * 128 + lp;   // 0 .. BATCH*NPTS-1
    const int b = idx / NPTS;
    const int p = idx % NPTS;
    const int h = p >> 5;

    float re = 0.0f, im = 0.0f;
    const int sbase = half * 8;
#pragma unroll
    for (int s = 0; s < 8; s++) {
        float2 v = g_partial[(b * NSPLIT + sbase + s) * NPTS + p];
        re += v.x; im += v.y;
    }
    sPart[tid] = make_float2(re, im);
    __syncthreads();
    const float2 o = sPart[tid ^ 128];
    // match previous summation order: (stages 0-7) + (stages 8-15)
    if (half == 0) { re = re + o.x; im = im + o.y; }
    else           { re = o.x + re; im = o.y + im; }

    const float m2 = re * re + im * im;
    const bool nul = (h == GH - 1) || (m2 == 0.0f);   // padded row or zero
    if (half == 0) {
        out[idx] = nul ? 0.0f : log1pf(sqrtf(m2));                  // mag
    } else {
        out[BATCH * NPTS + idx] = nul ? 0.0f : atan2f(im, re);      // phase
    }
}

extern "C" void kernel_launch(void* const* d_in, const int* in_sizes, int n_in,
                              void* d_out, int out_size) {
    const float* tris    = (const float*)d_in[0];   // [64,128,3,2] f32
    const int*   lengths = (const int*)d_in[1];     // [64] i32
    float* out = (float*)d_out;                     // 262144 f32: mag then phase

    pfc_init_grid_kernel<<<GH + GW, 1>>>();
    pfc_accum_kernel<<<BATCH * NSPLIT, NTHREADS>>>(tris, lengths);
    pfc_finalize_kernel<<<(BATCH * NPTS) / 128, 256>>>(out);
}

// round 13
// speedup vs baseline: 1.8428x; 1.0764x over previous
#include <cuda_runtime.h>
#include <math.h>

#define BATCH   64
#define MAXN    128
#define GH      64
#define GW      32
#define NPTS    2048        // GH*GW
#define NSPLIT  16
#define MAXCHUNK 8          // ceil(MAXN / NSPLIT)
#define NTHREADS 256
#define PPT     8           // NPTS / NTHREADS

typedef unsigned long long u64;

// Partial accumulators: [BATCH][NSPLIT][NPTS] complex (float2) = 16 MB
__device__ float2 g_partial[BATCH * NSPLIT * NPTS];

// ---- packed f32x2 helpers ----
__device__ __forceinline__ u64 pk(float lo, float hi) {
    u64 r; asm("mov.b64 %0, {%1,%2};" : "=l"(r) : "f"(lo), "f"(hi)); return r;
}
__device__ __forceinline__ void upk(u64 v, float& lo, float& hi) {
    asm("mov.b64 {%0,%1}, %2;" : "=f"(lo), "=f"(hi) : "l"(v));
}
__device__ __forceinline__ u64 mul2(u64 a, u64 b) {
    u64 d; asm("mul.rn.f32x2 %0, %1, %2;" : "=l"(d) : "l"(a), "l"(b)); return d;
}
__device__ __forceinline__ u64 fma2(u64 a, u64 b, u64 c) {
    u64 d; asm("fma.rn.f32x2 %0, %1, %2, %3;" : "=l"(d) : "l"(a), "l"(b), "l"(c)); return d;
}
__device__ __forceinline__ u64 add2(u64 a, u64 b) {
    u64 d; asm("add.rn.f32x2 %0, %1, %2;" : "=l"(d) : "l"(a), "l"(b)); return d;
}

// pos_w[k] = 0.1 * 10^(k/30), float path: one MUFU EX2, <=3 ulp.
// log2(10)/30 = 0.11073093649624542...
__device__ __forceinline__ float pos_w_fast(int k) {
    return 0.1f * exp2f((float)k * 0.110730936496245417f);
}

struct Tri { float xq, yq, xr, yr, xs, ys, area, scale2; };

__global__ __launch_bounds__(NTHREADS)
void pfc_accum_kernel(const float* __restrict__ tris,
                      const int* __restrict__ lengths) {
    __shared__ float sWx[GH];
    __shared__ float sWy[GW];
    __shared__ Tri   sTri[MAXCHUNK];
    __shared__ float4 sRowQ[2][GH], sRowR[2][GH];
    __shared__ float2 sRowP[2][GH];
    __shared__ float4 sColQ[2][GW], sColR[2][GW];
    __shared__ float2 sColP[2][GW];

    const int tid = threadIdx.x;
    const int b   = blockIdx.x >> 4;        // / NSPLIT
    const int s   = blockIdx.x & (NSPLIT - 1);

    // Build frequency grid in-block, float-only (cheap: one EX2 per thread).
    // Exact zeros (wx=0 at h=31, pad h=63; wy=0 at w=0) are written literally,
    // preserving the reference's mask structure.
    if (tid < GH) {
        int h = tid;
        float v;
        if (h < 31)       v = -pos_w_fast(30 - h);
        else if (h == 31) v = 0.0f;
        else if (h <= 62) v = pos_w_fast(h - 32);
        else              v = 0.0f;           // padded row
        sWx[h] = v;
    } else if (tid < GH + GW) {
        int w = tid - GH;
        sWy[w] = (w == 0) ? 0.0f : pos_w_fast(w - 1);
    }

    const float TWO_PI   = 6.28318530717958648f;
    const float FOUR_PI2 = 4.0f * 3.14159274101257324f * 3.14159274101257324f;

    const int len  = lengths[b];
    // interleaved assignment: this split owns triangles s, s+16, s+32, ...
    const int ntri = (len > s) ? ((len - 1 - s) / NSPLIT + 1) : 0;

    if (tid < MAXCHUNK && tid < ntri) {
        const int t = s + tid * NSPLIT;
        const float* p = tris + (size_t)(b * MAXN + t) * 6;
        Tri tr;
        tr.xq = p[0]; tr.yq = p[1];
        tr.xr = p[2]; tr.yr = p[3];
        tr.xs = p[4]; tr.ys = p[5];
        float det = tr.xq * (tr.yr - tr.ys) + tr.xr * (tr.ys - tr.yq)
                  + tr.xs * (tr.yq - tr.yr);
        tr.area   = fabsf(0.5f * det);
        tr.scale2 = 2.0f * tr.area / FOUR_PI2;
        sTri[tid] = tr;
    }
    __syncthreads();

    const int w     = tid & 31;
    const int hbase = (tid >> 5) * PPT;

    u64 acc[PPT];
#pragma unroll
    for (int k = 0; k < PPT; k++) acc[k] = 0ull;

    for (int j = 0; j < ntri; j++) {
        const Tri tr = sTri[j];   // broadcast
        const int buf = j & 1;

        // ---- build factored vertex-phasor tables (288 sincos, coop) ----
        if (tid < 192) {
            int h = tid & 63;
            int which = tid >> 6;               // 0:Q 1:R 2:P(=S row)
            float wx = sWx[h];
            float arg, lin;
            if (which == 0)      { arg = wx * tr.xq; lin = wx * (tr.xr - tr.xq); }
            else if (which == 1) { arg = wx * tr.xr; lin = wx * (tr.xs - tr.xr); }
            else                 { arg = wx * tr.xs; lin = 0.0f; }
            float sn, cs;
            sincosf(-TWO_PI * arg, &sn, &cs);
            if (which == 0)      sRowQ[buf][h] = make_float4(cs, sn, -sn, lin);
            else if (which == 1) sRowR[buf][h] = make_float4(cs, sn, -sn, lin);
            else                 sRowP[buf][h] = make_float2(cs, sn);
        } else {
            int ww = tid & 31;
            float wy = sWy[ww];
            float arg, lin;
            if (tid < 224) { arg = wy * tr.yq; lin = wy * (tr.yr - tr.yq); }
            else           { arg = wy * tr.yr; lin = wy * (tr.ys - tr.yr); }
            float sn, cs;
            sincosf(-TWO_PI * arg, &sn, &cs);
            if (tid < 224) sColQ[buf][ww] = make_float4(cs, sn, lin, 0.0f);
            else           sColR[buf][ww] = make_float4(cs, sn, lin, 0.0f);
        }
        if (tid < 32) {                         // second job: colS phasor
            float wy = sWy[tid];
            float sn, cs;
            sincosf(-TWO_PI * (wy * tr.ys), &sn, &cs);
            sColP[buf][tid] = make_float2(cs, sn);
        }
        __syncthreads();   // single barrier per triangle (double buffered)

        // ---- per-triangle column prep (done once, reused over 8 h's) ----
        const float4 cQ = sColQ[buf][w];
        const float4 cR = sColR[buf][w];
        const float2 cS = sColP[buf][w];
        const u64 cQcdN = pk(-cQ.x, -cQ.y);     // negated -> produces -Eq
        const u64 cQdcN = pk(-cQ.y, -cQ.x);
        const u64 cRcd  = pk( cR.x,  cR.y);     // positive -> Er
        const u64 cRdc  = pk( cR.y,  cR.x);
        const u64 cScdN = pk(-cS.x, -cS.y);     // negated -> -Es
        const u64 cSdcN = pk(-cS.y, -cS.x);
        const float cLinU = cQ.z;
        const float cLinV = cR.z;
        const float area   = tr.area;
        const float scale2 = tr.scale2;

#pragma unroll
        for (int k = 0; k < PPT; k++) {
            const int h = hbase + k;            // uniform across the warp
            const float4 rQ = sRowQ[buf][h];
            const float4 rR = sRowR[buf][h];
            const float2 rP = sRowP[buf][h];

            const float U_ = rQ.w + cLinU;
            const float V_ = rR.w + cLinV;
            const float S  = U_ + V_;

            // vertex phasors (row x col complex product), Q and S negated
            u64 EqN = mul2(pk(rQ.x, rQ.x), cQcdN);
            EqN     = fma2(pk(rQ.z, rQ.y), cQdcN, EqN);
            u64 Er  = mul2(pk(rR.x, rR.x), cRcd);
            Er      = fma2(pk(rR.z, rR.y), cRdc, Er);
            u64 EsN = mul2(pk(rP.x, rP.x), cScdN);
            EsN     = fma2(pk(-rP.y, rP.y), cSdcN, EsN);

            if (U_ != 0.0f && V_ != 0.0f && S != 0.0f) {          // normal
                // p2 = -U_*Es + S*Er - V_*Eq  =  U_*EsN + S*Er + V_*EqN
                u64 p2 = mul2(pk(U_, U_), EsN);
                p2 = fma2(pk(S, S), Er, p2);
                p2 = fma2(pk(V_, V_), EqN, p2);
                const float scale = __fdividef(scale2, U_ * V_ * S);
                acc[k] = fma2(pk(scale, scale), p2, acc[k]);
            } else {
                float eqr, eqi, esr, esi, erre, erim;
                upk(EqN, eqr, eqi); eqr = -eqr; eqi = -eqi;
                upk(EsN, esr, esi); esr = -esr; esi = -esi;
                upk(Er, erre, erim);
                if (U_ == 0.0f && V_ == 0.0f) {                   // zero
                    acc[k] = add2(acc[k], pk(area, 0.0f));
                } else if (S == 0.0f) {                           // diag
                    const float scale = -__fdividef(scale2, U_ * U_);
                    const float wim = TWO_PI * U_;
                    const float tre = erre - eqr - wim * eqi;
                    const float tim = erim - eqi + wim * eqr;
                    acc[k] = fma2(pk(scale, scale), pk(tre, tim), acc[k]);
                } else if (U_ == 0.0f) {                          // u-mask
                    const float scale = -__fdividef(scale2, V_ * V_);
                    const float wim = TWO_PI * V_;
                    const float tre = esr - eqr - wim * eqi;
                    const float tim = esi - eqi + wim * eqr;
                    acc[k] = fma2(pk(scale, scale), pk(tre, tim), acc[k]);
                } else {                                          // v-mask
                    const float scale = __fdividef(scale2, U_ * U_);
                    const float wim = TWO_PI * U_;
                    const float tre = erre - wim * erim - eqr;
                    const float tim = erim + wim * erre - eqi;
                    acc[k] = fma2(pk(scale, scale), pk(tre, tim), acc[k]);
                }
            }
        }
        // next build writes the other buffer; the barrier at the top of
        // iteration j+1 orders build(j+2) after eval(j).
    }

#pragma unroll
    for (int k = 0; k < PPT; k++) {
        const int p = (hbase + k) * GW + w;
        *reinterpret_cast<u64*>(&g_partial[(b * NSPLIT + s) * NPTS + p]) = acc[k];
    }
}

// Two threads per point: each sums 8 of the 16 stages, exchange via smem,
// then half-0 writes mag and half-1 writes phase.
__global__ __launch_bounds__(256)
void pfc_finalize_kernel(float* __restrict__ out) {
    __shared__ float2 sPart[256];
    const int tid  = threadIdx.x;
    const int lp   = tid & 127;               // local point
    const int half = tid >> 7;                // 0: stages 0-7, 1: stages 8-15
    const int idx  = blockIdx.x * 128 + lp;   // 0 .. BATCH*NPTS-1
    const int b = idx / NPTS;
    const int p = idx % NPTS;
    const int h = p >> 5;

    float re = 0.0f, im = 0.0f;
    const int sbase = half * 8;
#pragma unroll
    for (int s = 0; s < 8; s++) {
        float2 v = g_partial[(b * NSPLIT + sbase + s) * NPTS + p];
        re += v.x; im += v.y;
    }
    sPart[tid] = make_float2(re, im);
    __syncthreads();
    const float2 o = sPart[tid ^ 128];
    // match previous summation order: (stages 0-7) + (stages 8-15)
    if (half == 0) { re = re + o.x; im = im + o.y; }
    else           { re = o.x + re; im = o.y + im; }

    const float m2 = re * re + im * im;
    const bool nul = (h == GH - 1) || (m2 == 0.0f);   // padded row or zero
    if (half == 0) {
        out[idx] = nul ? 0.0f : log1pf(sqrtf(m2));                  // mag
    } else {
        out[BATCH * NPTS + idx] = nul ? 0.0f : atan2f(im, re);      // phase
    }
}

extern "C" void kernel_launch(void* const* d_in, const int* in_sizes, int n_in,
                              void* d_out, int out_size) {
    const float* tris    = (const float*)d_in[0];   // [64,128,3,2] f32
    const int*   lengths = (const int*)d_in[1];     // [64] i32
    float* out = (float*)d_out;                     // 262144 f32: mag then phase

    pfc_accum_kernel<<<BATCH * NSPLIT, NTHREADS>>>(tris, lengths);
    pfc_finalize_kernel<<<(BATCH * NPTS) / 128, 256>>>(out);
}